// round 16
// baseline (speedup 1.0000x reference)
#include <cuda_runtime.h>
#include <cuda_bf16.h>
#include <math.h>
#include <stdint.h>

#define T_STEPS 200
#define BATCH   128
#define DIN     784
#define HID     500
#define NOUT    10
#define MROWS   (BATCH * T_STEPS)   // 25600
#define DECAY_M 0.77880078307140487f
#define EPS_BN  1e-5f
#define NSTATB  1600                 // 16 rows per block
#define KP1     832
#define KP2     512

#define ROWB    144
#define ASPL    (128 * ROWB)
#define BSPL    (64 * ROWB)
#define SMEM_B0 (3 * ASPL)
#define SMEM_TOT (SMEM_B0 + 3 * BSPL)   // 82944

// ------------------------- device scratch (no allocs allowed) ---------------
__device__ float g_buf0[MROWS * DIN];
__device__ float g_buf1[MROWS * HID];
__device__ float g_buf2[MROWS * HID];
__device__ float g_buf3[MROWS * NOUT];
__device__ double g_psumd[NSTATB * DIN];
__device__ double g_psqd [NSTATB * DIN];
__device__ float g_mean[DIN];
__device__ float g_rs[DIN];
__device__ __nv_bfloat16 g_Ah[MROWS * KP1];
__device__ __nv_bfloat16 g_Am[MROWS * KP1];
__device__ __nv_bfloat16 g_Al[MROWS * KP1];
__device__ __nv_bfloat16 g_Wh[800 * KP1];
__device__ __nv_bfloat16 g_Wm[800 * KP1];
__device__ __nv_bfloat16 g_Wl[800 * KP1];

__device__ __forceinline__ float* bufsel(int s) {
    return s == 0 ? g_buf0 : (s == 1 ? g_buf1 : g_buf2);
}

__device__ __forceinline__ void kmerge(float r, float& s, float& c) {
    float y = __fsub_rn(r, c);
    float t = __fadd_rn(s, y);
    c = __fsub_rn(__fsub_rn(t, s), y);
    s = t;
}

__device__ __forceinline__ void kacc2(float a, float b, float& s, float& c) {
    float y = __fmaf_rn(a, b, -c);
    float t = __fadd_rn(s, y);
    c = __fsub_rn(__fsub_rn(t, s), y);
    s = t;
}

__device__ __forceinline__ float sigmoid_exact(float x) {
    return __fdiv_rn(1.0f, __fadd_rn(1.0f, expf(-x)));
}

// ------------------------- bf16 3-way split ---------------------------------
__device__ __forceinline__ void bsplit(float a, __nv_bfloat16& h,
                                       __nv_bfloat16& m, __nv_bfloat16& l) {
    h = __float2bfloat16(a);
    float r1 = __fsub_rn(a, __bfloat162float(h));
    m = __float2bfloat16(r1);
    float r2 = __fsub_rn(r1, __bfloat162float(m));
    l = __float2bfloat16(r2);
}

// ---- coalesced tiled split of inputs [B, DIN, T] -> split rows (b*T+t, k) --
__global__ void split_a_mlp_t_kernel(const float* __restrict__ In) {
    __shared__ float tile[32][33];
    int b  = blockIdx.x;
    int t0 = blockIdx.y * 32;
    int k0 = blockIdx.z * 32;
#pragma unroll
    for (int i = 0; i < 4; i++) {
        int k = k0 + threadIdx.y + i * 8;
        int t = t0 + threadIdx.x;
        float v = 0.f;
        if (k < DIN && t < T_STEPS)
            v = In[b * (DIN * T_STEPS) + k * T_STEPS + t];
        tile[threadIdx.y + i * 8][threadIdx.x] = v;
    }
    __syncthreads();
#pragma unroll
    for (int i = 0; i < 4; i++) {
        int t = t0 + threadIdx.y + i * 8;
        int k = k0 + threadIdx.x;
        if (t < T_STEPS) {
            float v = tile[threadIdx.x][threadIdx.y + i * 8];
            __nv_bfloat16 h, m, l;
            bsplit(v, h, m, l);
            int soff = (b * T_STEPS + t) * KP1 + k;
            g_Ah[soff] = h; g_Am[soff] = m; g_Al[soff] = l;
        }
    }
}

__global__ void split_w_kernel(const float* __restrict__ W, int N, int K, int KP) {
    int idx = blockIdx.x * blockDim.x + threadIdx.x;
    if (idx >= N * KP) return;
    int n = idx / KP, k = idx - n * KP;
    float v = (k < K) ? W[n * K + k] : 0.f;
    __nv_bfloat16 h, m, l;
    bsplit(v, h, m, l);
    g_Wh[idx] = h; g_Wm[idx] = m; g_Wl[idx] = l;
}

// zero KP2 pad columns (alias stale KP1-layout data each replay)
__global__ void zero_pad2_kernel() {
    int idx = blockIdx.x * blockDim.x + threadIdx.x;
    if (idx >= MROWS * (KP2 - HID)) return;
    int r = idx / (KP2 - HID), j = idx - r * (KP2 - HID);
    int off = r * KP2 + HID + j;
    g_Ah[off] = __float2bfloat16(0.f);
    g_Am[off] = __float2bfloat16(0.f);
    g_Al[off] = __float2bfloat16(0.f);
}

// ======================= mma.sync bf16x6 GEMM (chunk-compensated) ===========
// Grid: (n-tiles, m-tiles) -- consecutive CTAs share the same A tile (L2 reuse)
__device__ __forceinline__ uint32_t sm2u32(const void* p) {
    uint32_t a;
    asm("{ .reg .u64 t; cvta.to.shared.u64 t, %1; cvt.u32.u64 %0, t; }"
        : "=r"(a) : "l"(p));
    return a;
}

#define LDMX4(r0, r1, r2, r3, addr) \
    asm volatile("ldmatrix.sync.aligned.m8n8.x4.shared.b16 {%0,%1,%2,%3}, [%4];" \
                 : "=r"(r0), "=r"(r1), "=r"(r2), "=r"(r3) : "r"(addr))

#define MMA16816(c, a, b0, b1) \
    asm volatile("mma.sync.aligned.m16n8k16.row.col.f32.bf16.bf16.f32 " \
                 "{%0,%1,%2,%3}, {%4,%5,%6,%7}, {%8,%9}, {%0,%1,%2,%3};" \
                 : "+f"((c)[0]), "+f"((c)[1]), "+f"((c)[2]), "+f"((c)[3]) \
                 : "r"((a)[0]), "r"((a)[1]), "r"((a)[2]), "r"((a)[3]), \
                   "r"(b0), "r"(b1))

__global__ void __launch_bounds__(256) mma_gemm_kernel(
    const float* __restrict__ bias, int csel, int N, int KP) {
    extern __shared__ char smem[];
    float* Cdst = bufsel(csel);
    uint32_t sb = sm2u32(smem);
    int tid = threadIdx.x, w = tid >> 5, lane = tid & 31;
    int n0 = blockIdx.x * 64, m0 = blockIdx.y * 128;   // x = n (fast) for A reuse

    const __nv_bfloat16* Asrc[3] = {g_Ah, g_Am, g_Al};
    const __nv_bfloat16* Bsrc[3] = {g_Wh, g_Wm, g_Wl};

    float ps[8][4], pc[8][4];
#pragma unroll
    for (int i = 0; i < 8; i++)
#pragma unroll
        for (int j = 0; j < 4; j++) { ps[i][j] = 0.f; pc[i][j] = 0.f; }

    int aRow = w * 16 + (lane & 7) + ((lane >> 3) & 1) * 8;
    int aCol = ((lane >> 4) & 1) * 16;
    int bRow = (lane & 7) + ((lane >> 4) & 1) * 8;
    int bCol = ((lane >> 3) & 1) * 16;

    const int nch = KP / 64;
    for (int ch = 0; ch < nch; ch++) {
        const int k0 = ch * 64;
#pragma unroll
        for (int l = 0; l < 12; l++) {
            int e = tid + l * 256;
            int s = e >> 10, rem = e & 1023, m = rem >> 3, j = rem & 7;
            uint4 v = *reinterpret_cast<const uint4*>(
                Asrc[s] + (size_t)(m0 + m) * KP + k0 + j * 8);
            *reinterpret_cast<uint4*>(smem + s * ASPL + m * ROWB + j * 16) = v;
        }
#pragma unroll
        for (int l = 0; l < 6; l++) {
            int e = tid + l * 256;
            int s = e >> 9, rem = e & 511, n = rem >> 3, j = rem & 7;
            uint4 v = make_uint4(0u, 0u, 0u, 0u);
            if (n0 + n < N)
                v = *reinterpret_cast<const uint4*>(
                    Bsrc[s] + (size_t)(n0 + n) * KP + k0 + j * 8);
            *reinterpret_cast<uint4*>(smem + SMEM_B0 + s * BSPL + n * ROWB + j * 16) = v;
        }
        __syncthreads();

        float acc[8][4];
#pragma unroll
        for (int i = 0; i < 8; i++)
#pragma unroll
            for (int j = 0; j < 4; j++) acc[i][j] = 0.f;

#pragma unroll
        for (int ks = 0; ks < 4; ks++) {
            uint32_t af[3][4];
#pragma unroll
            for (int s = 0; s < 3; s++)
                LDMX4(af[s][0], af[s][1], af[s][2], af[s][3],
                      sb + s * ASPL + aRow * ROWB + ks * 32 + aCol);
#pragma unroll
            for (int q = 0; q < 4; q++) {
                uint32_t bfr[3][4];
#pragma unroll
                for (int s = 0; s < 3; s++)
                    LDMX4(bfr[s][0], bfr[s][1], bfr[s][2], bfr[s][3],
                          sb + SMEM_B0 + s * BSPL + (q * 16 + bRow) * ROWB +
                          ks * 32 + bCol);
                const int pa[6] = {0, 2, 1, 0, 1, 0};
                const int pb[6] = {2, 0, 1, 1, 0, 0};
#pragma unroll
                for (int p = 0; p < 6; p++) {
                    MMA16816(acc[2 * q],     af[pa[p]], bfr[pb[p]][0], bfr[pb[p]][1]);
                    MMA16816(acc[2 * q + 1], af[pa[p]], bfr[pb[p]][2], bfr[pb[p]][3]);
                }
            }
        }
#pragma unroll
        for (int i = 0; i < 8; i++)
#pragma unroll
            for (int j = 0; j < 4; j++) kmerge(acc[i][j], ps[i][j], pc[i][j]);
        __syncthreads();
    }

    int r = lane >> 2, cp = (lane & 3) * 2;
#pragma unroll
    for (int nb = 0; nb < 8; nb++) {
        int n = n0 + nb * 8 + cp;
        int m = m0 + w * 16 + r;
        if (n < N) {
            Cdst[(size_t)m * N + n] =
                __fadd_rn(__fsub_rn(ps[nb][0], pc[nb][0]), bias[n]);
            Cdst[(size_t)(m + 8) * N + n] =
                __fadd_rn(__fsub_rn(ps[nb][2], pc[nb][2]), bias[n]);
        }
        if (n + 1 < N) {
            Cdst[(size_t)m * N + n + 1] =
                __fadd_rn(__fsub_rn(ps[nb][1], pc[nb][1]), bias[n + 1]);
            Cdst[(size_t)(m + 8) * N + n + 1] =
                __fadd_rn(__fsub_rn(ps[nb][3], pc[nb][3]), bias[n + 1]);
        }
    }
}

// ------------------------- BN stats: fp64, 16 rows per block ----------------
__global__ void bn_stats_kernel() {
    int blk = blockIdx.x;
    int tid = threadIdx.x;
    double ls[4] = {0.0, 0.0, 0.0, 0.0};
    double lq[4] = {0.0, 0.0, 0.0, 0.0};
    int r0 = blk * (MROWS / NSTATB);
    for (int rr = 0; rr < MROWS / NSTATB; rr += 4) {
        float v[4][4];
#pragma unroll
        for (int u = 0; u < 4; u++) {
            const float* row = g_buf0 + (size_t)(r0 + rr + u) * DIN;
#pragma unroll
            for (int j = 0; j < 4; j++) {
                int c = tid + j * 256;
                v[u][j] = (c < DIN) ? row[c] : 0.f;
            }
        }
#pragma unroll
        for (int u = 0; u < 4; u++)
#pragma unroll
            for (int j = 0; j < 4; j++) {
                double d = (double)v[u][j];
                ls[j] += d;
                lq[j] += d * d;
            }
    }
#pragma unroll
    for (int j = 0; j < 4; j++) {
        int c = tid + j * 256;
        if (c < DIN) {
            g_psumd[blk * DIN + c] = ls[j];
            g_psqd [blk * DIN + c] = lq[j];
        }
    }
}

__global__ void bn_fin_kernel() {
    int c = blockIdx.x * blockDim.x + threadIdx.x;
    if (c >= DIN) return;
    double s = 0.0, q = 0.0;
    for (int i = 0; i < NSTATB; i++) {
        s += g_psumd[i * DIN + c];
        q += g_psqd [i * DIN + c];
    }
    float sumf = (float)s;
    g_mean[c] = __fdiv_rn(sumf, (float)MROWS);
    double meand = s / (double)MROWS;
    double vard = q / (double)MROWS - meand * meand;
    float var = (float)vard;
    g_rs[c] = rsqrtf(__fadd_rn(var, EPS_BN));
}

// ------- fused BN apply + sigmoid + axon1, 2 channels/thread, bf16 out ------
__global__ void axon1_bn_split_kernel(const float* __restrict__ gamma,
                                      const float* __restrict__ beta,
                                      const float* __restrict__ a1,
                                      const float* __restrict__ a2) {
    const int HD = DIN / 2;   // 392
    int idx = blockIdx.x * blockDim.x + threadIdx.x;
    if (idx >= BATCH * HD) return;
    int b = idx / HD, c2 = idx - b * HD;
    int c = c2 * 2;
    float A1x = a1[c], A1y = a1[c + 1];
    float A2x = a2[c], A2y = a2[c + 1];
    float mnx = g_mean[c], mny = g_mean[c + 1];
    float rsx = g_rs[c], rsy = g_rs[c + 1];
    float gmx = gamma[c], gmy = gamma[c + 1];
    float btx = beta[c], bty = beta[c + 1];
    float p1x = 0.f, p2x = 0.f, p1y = 0.f, p2y = 0.f;
    const float2* src = reinterpret_cast<const float2*>(
        g_buf0 + (size_t)b * T_STEPS * DIN + c);
    __nv_bfloat162* dh = reinterpret_cast<__nv_bfloat162*>(
        g_Ah + (size_t)b * T_STEPS * KP1 + c);
    __nv_bfloat162* dm = reinterpret_cast<__nv_bfloat162*>(
        g_Am + (size_t)b * T_STEPS * KP1 + c);
    __nv_bfloat162* dl = reinterpret_cast<__nv_bfloat162*>(
        g_Al + (size_t)b * T_STEPS * KP1 + c);
    for (int t = 0; t < T_STEPS; t++) {
        float2 z = *src;
        src += DIN / 2;
        float vx = __fadd_rn(__fmul_rn(__fmul_rn(gmx, __fsub_rn(z.x, mnx)), rsx), btx);
        float vy = __fadd_rn(__fmul_rn(__fmul_rn(gmy, __fsub_rn(z.y, mny)), rsy), bty);
        float xx = sigmoid_exact(vx);
        float xy = sigmoid_exact(vy);
        float px = __fadd_rn(__fadd_rn(__fmul_rn(A1x, p1x), __fmul_rn(A2x, p2x)), xx);
        float py = __fadd_rn(__fadd_rn(__fmul_rn(A1y, p1y), __fmul_rn(A2y, p2y)), xy);
        __nv_bfloat16 hx, mx, lx, hy, my, ly;
        bsplit(px, hx, mx, lx);
        bsplit(py, hy, my, ly);
        __nv_bfloat162 hv; hv.x = hx; hv.y = hy;
        __nv_bfloat162 mv; mv.x = mx; mv.y = my;
        __nv_bfloat162 lv; lv.x = lx; lv.y = ly;
        *dh = hv; *dm = mv; *dl = lv;
        dh += KP1 / 2; dm += KP1 / 2; dl += KP1 / 2;
        p2x = p1x; p1x = px;
        p2y = p1y; p1y = py;
    }
}

// ---- fused LIF + mask + axon, 2 ch/thread, writes bf16x3 (KP2 layout) ------
__global__ void lif_axon_split_kernel(int bsel, const float* __restrict__ mask,
                                      const float* __restrict__ a1,
                                      const float* __restrict__ a2) {
    const int HD = HID / 2;   // 250
    float* buf = bufsel(bsel);
    int idx = blockIdx.x * blockDim.x + threadIdx.x;
    if (idx >= BATCH * HD) return;
    int b = idx / HD, c2 = idx - b * HD;
    int c = c2 * 2;
    float A1x = a1[c], A1y = a1[c + 1];
    float A2x = a2[c], A2y = a2[c + 1];
    float vx = 0.f, spx = 0.f, vy = 0.f, spy = 0.f;
    float p1x = 0.f, p2x = 0.f, p1y = 0.f, p2y = 0.f;
    const float2* src = reinterpret_cast<const float2*>(
        buf + (size_t)b * T_STEPS * HID + c);
    __nv_bfloat162* dh = reinterpret_cast<__nv_bfloat162*>(
        g_Ah + (size_t)b * T_STEPS * KP2 + c);
    __nv_bfloat162* dm = reinterpret_cast<__nv_bfloat162*>(
        g_Am + (size_t)b * T_STEPS * KP2 + c);
    __nv_bfloat162* dl = reinterpret_cast<__nv_bfloat162*>(
        g_Al + (size_t)b * T_STEPS * KP2 + c);
    const float* mrow0 = mask + (size_t)(b * HID + c) * T_STEPS;
    const float* mrow1 = mrow0 + T_STEPS;
    for (int t = 0; t < T_STEPS; t++) {
        float2 z = *src;
        src += HID / 2;
        vx = __fadd_rn(__fmul_rn(__fmul_rn(DECAY_M, vx), __fsub_rn(1.0f, spx)), z.x);
        vy = __fadd_rn(__fmul_rn(__fmul_rn(DECAY_M, vy), __fsub_rn(1.0f, spy)), z.y);
        spx = (vx > 1.0f) ? 1.0f : 0.0f;
        spy = (vy > 1.0f) ? 1.0f : 0.0f;
        float xx = __fmul_rn(spx, mrow0[t]);
        float xy = __fmul_rn(spy, mrow1[t]);
        float px = __fadd_rn(__fadd_rn(__fmul_rn(A1x, p1x), __fmul_rn(A2x, p2x)), xx);
        float py = __fadd_rn(__fadd_rn(__fmul_rn(A1y, p1y), __fmul_rn(A2y, p2y)), xy);
        __nv_bfloat16 hx, mx, lx, hy, my, ly;
        bsplit(px, hx, mx, lx);
        bsplit(py, hy, my, ly);
        __nv_bfloat162 hv; hv.x = hx; hv.y = hy;
        __nv_bfloat162 mv; mv.x = mx; mv.y = my;
        __nv_bfloat162 lv; lv.x = lx; lv.y = ly;
        *dh = hv; *dm = mv; *dl = lv;
        dh += KP2 / 2; dm += KP2 / 2; dl += KP2 / 2;
        p2x = p1x; p1x = px;
        p2y = p1y; p1y = py;
    }
}

// ---- fused LIF + mask + axon, 2 ch/thread, fp32 out (feeds gemm3) ----------
__global__ void lif_axon_kernel(int bsel, const float* __restrict__ mask,
                                const float* __restrict__ a1,
                                const float* __restrict__ a2) {
    const int HD = HID / 2;
    float* buf = bufsel(bsel);
    int idx = blockIdx.x * blockDim.x + threadIdx.x;
    if (idx >= BATCH * HD) return;
    int b = idx / HD, c2 = idx - b * HD;
    int c = c2 * 2;
    float A1x = a1[c], A1y = a1[c + 1];
    float A2x = a2[c], A2y = a2[c + 1];
    float vx = 0.f, spx = 0.f, vy = 0.f, spy = 0.f;
    float p1x = 0.f, p2x = 0.f, p1y = 0.f, p2y = 0.f;
    float2* src = reinterpret_cast<float2*>(buf + (size_t)b * T_STEPS * HID + c);
    const float* mrow0 = mask + (size_t)(b * HID + c) * T_STEPS;
    const float* mrow1 = mrow0 + T_STEPS;
    for (int t = 0; t < T_STEPS; t++) {
        float2 z = *src;
        vx = __fadd_rn(__fmul_rn(__fmul_rn(DECAY_M, vx), __fsub_rn(1.0f, spx)), z.x);
        vy = __fadd_rn(__fmul_rn(__fmul_rn(DECAY_M, vy), __fsub_rn(1.0f, spy)), z.y);
        spx = (vx > 1.0f) ? 1.0f : 0.0f;
        spy = (vy > 1.0f) ? 1.0f : 0.0f;
        float px = __fadd_rn(__fadd_rn(__fmul_rn(A1x, p1x), __fmul_rn(A2x, p2x)),
                             __fmul_rn(spx, mrow0[t]));
        float py = __fadd_rn(__fadd_rn(__fmul_rn(A1y, p1y), __fmul_rn(A2y, p2y)),
                             __fmul_rn(spy, mrow1[t]));
        float2 o; o.x = px; o.y = py;
        *src = o;
        src += HID / 2;
        p2x = p1x; p1x = px;
        p2y = p1y; p1y = py;
    }
}

// ------------------------- GEMM3 (N=10): compensated ------------------------
__global__ void __launch_bounds__(256) gemm3_kernel(
    const float* __restrict__ W3, const float* __restrict__ b3) {
    __shared__ float sW[NOUT][HID];
    int tid = threadIdx.x;
    for (int i = tid; i < NOUT * HID; i += 256) sW[i / HID][i % HID] = W3[i];
    __syncthreads();
    int idx = blockIdx.x * 256 + tid;
    int r = idx / NOUT, o = idx - r * NOUT;
    const float* a = g_buf2 + r * HID;
    float s = 0.f, c = 0.f;
    for (int k = 0; k < HID; k++) kacc2(a[k], sW[o][k], s, c);
    float acc = __fsub_rn(s, c);
    g_buf3[r * NOUT + o] = __fadd_rn(acc, b3[o]);
}

// ------------------------- final LIF + output transpose [B,10,T] ------------
__global__ void lif3_out_kernel(float* __restrict__ out) {
    int idx = blockIdx.x * blockDim.x + threadIdx.x;
    if (idx >= BATCH * NOUT) return;
    int b = idx / NOUT, o = idx - b * NOUT;
    float v = 0.f, s = 0.f;
    for (int t = 0; t < T_STEPS; t++) {
        float z = g_buf3[(b * T_STEPS + t) * NOUT + o];
        v = __fadd_rn(__fmul_rn(__fmul_rn(DECAY_M, v), __fsub_rn(1.0f, s)), z);
        s = (v > 1.0f) ? 1.0f : 0.0f;
        out[(b * NOUT + o) * T_STEPS + t] = s;
    }
}

// ------------------------- launch -------------------------------------------
extern "C" void kernel_launch(void* const* d_in, const int* in_sizes, int n_in,
                              void* d_out, int out_size) {
    const float* inputs = (const float*)d_in[0];
    const float* W_mlp  = (const float*)d_in[1];
    const float* b_mlp  = (const float*)d_in[2];
    const float* gamma  = (const float*)d_in[3];
    const float* beta   = (const float*)d_in[4];
    const float* a1_1   = (const float*)d_in[5];
    const float* a2_1   = (const float*)d_in[6];
    const float* W1     = (const float*)d_in[7];
    const float* b1     = (const float*)d_in[8];
    const float* a1_2   = (const float*)d_in[9];
    const float* a2_2   = (const float*)d_in[10];
    const float* W2     = (const float*)d_in[11];
    const float* b2     = (const float*)d_in[12];
    const float* a1_3   = (const float*)d_in[13];
    const float* a2_3   = (const float*)d_in[14];
    const float* W3     = (const float*)d_in[15];
    const float* b3     = (const float*)d_in[16];
    const float* mask1  = (const float*)d_in[17];
    const float* mask2  = (const float*)d_in[18];
    float* out = (float*)d_out;

    static int smem_set = 0;
    if (!smem_set) {
        cudaFuncSetAttribute(mma_gemm_kernel,
                             cudaFuncAttributeMaxDynamicSharedMemorySize, SMEM_TOT);
        smem_set = 1;
    }

    // ---- GEMM MLP  (grid: x = n-tiles for A-tile L2 reuse)
    split_a_mlp_t_kernel<<<dim3(BATCH, 7, 26), dim3(32, 8)>>>(inputs);
    split_w_kernel<<<(DIN * KP1 + 255) / 256, 256>>>(W_mlp, DIN, DIN, KP1);
    mma_gemm_kernel<<<dim3((DIN + 63) / 64, MROWS / 128), 256, SMEM_TOT>>>(
        b_mlp, 0, DIN, KP1);

    bn_stats_kernel<<<NSTATB, 256>>>();
    bn_fin_kernel<<<(DIN + 255) / 256, 256>>>();
    axon1_bn_split_kernel<<<(BATCH * (DIN / 2) + 255) / 256, 256>>>(
        gamma, beta, a1_1, a2_1);

    // ---- GEMM1
    split_w_kernel<<<(HID * KP1 + 255) / 256, 256>>>(W1, HID, DIN, KP1);
    mma_gemm_kernel<<<dim3((HID + 63) / 64, MROWS / 128), 256, SMEM_TOT>>>(
        b1, 1, HID, KP1);
    lif_axon_split_kernel<<<(BATCH * (HID / 2) + 255) / 256, 256>>>(
        1, mask1, a1_2, a2_2);
    zero_pad2_kernel<<<(MROWS * (KP2 - HID) + 255) / 256, 256>>>();

    // ---- GEMM2
    split_w_kernel<<<(HID * KP2 + 255) / 256, 256>>>(W2, HID, HID, KP2);
    mma_gemm_kernel<<<dim3((HID + 63) / 64, MROWS / 128), 256, SMEM_TOT>>>(
        b2, 2, HID, KP2);
    lif_axon_kernel<<<(BATCH * (HID / 2) + 255) / 256, 256>>>(
        2, mask2, a1_3, a2_3);

    // ---- GEMM3 + output
    gemm3_kernel<<<MROWS * NOUT / 256, 256>>>(W3, b3);
    lif3_out_kernel<<<(BATCH * NOUT + 255) / 256, 256>>>(out);
}

// round 17
// speedup vs baseline: 1.0531x; 1.0531x over previous
#include <cuda_runtime.h>
#include <cuda_bf16.h>
#include <math.h>
#include <stdint.h>

#define T_STEPS 200
#define BATCH   128
#define DIN     784
#define HID     500
#define NOUT    10
#define MROWS   (BATCH * T_STEPS)   // 25600
#define DECAY_M 0.77880078307140487f
#define EPS_BN  1e-5f
#define NSTATB  1600
#define KP1     832
#define KP2     512

#define ROWB    144
#define ASPL    (128 * ROWB)
#define BSPL    (64 * ROWB)
#define SMEM_B0 (3 * ASPL)
#define BUFSZ   (SMEM_B0 + 3 * BSPL)    // 82944 per buffer
#define SMEM_TOT (2 * BUFSZ)            // 165888 (double buffered)

// ------------------------- device scratch (no allocs allowed) ---------------
__device__ float g_buf0[MROWS * DIN];
__device__ float g_buf1[MROWS * HID];
__device__ float g_buf2[MROWS * HID];
__device__ float g_buf3[MROWS * NOUT];
__device__ double g_psumd[NSTATB * DIN];
__device__ double g_psqd [NSTATB * DIN];
__device__ float g_mean[DIN];
__device__ float g_rs[DIN];
__device__ __nv_bfloat16 g_Ah[MROWS * KP1];
__device__ __nv_bfloat16 g_Am[MROWS * KP1];
__device__ __nv_bfloat16 g_Al[MROWS * KP1];
__device__ __nv_bfloat16 g_Wh[800 * KP1];
__device__ __nv_bfloat16 g_Wm[800 * KP1];
__device__ __nv_bfloat16 g_Wl[800 * KP1];

__device__ __forceinline__ float* bufsel(int s) {
    return s == 0 ? g_buf0 : (s == 1 ? g_buf1 : g_buf2);
}

__device__ __forceinline__ void kmerge(float r, float& s, float& c) {
    float y = __fsub_rn(r, c);
    float t = __fadd_rn(s, y);
    c = __fsub_rn(__fsub_rn(t, s), y);
    s = t;
}

__device__ __forceinline__ void kacc2(float a, float b, float& s, float& c) {
    float y = __fmaf_rn(a, b, -c);
    float t = __fadd_rn(s, y);
    c = __fsub_rn(__fsub_rn(t, s), y);
    s = t;
}

__device__ __forceinline__ float sigmoid_exact(float x) {
    return __fdiv_rn(1.0f, __fadd_rn(1.0f, expf(-x)));
}

// ------------------------- bf16 3-way split ---------------------------------
__device__ __forceinline__ void bsplit(float a, __nv_bfloat16& h,
                                       __nv_bfloat16& m, __nv_bfloat16& l) {
    h = __float2bfloat16(a);
    float r1 = __fsub_rn(a, __bfloat162float(h));
    m = __float2bfloat16(r1);
    float r2 = __fsub_rn(r1, __bfloat162float(m));
    l = __float2bfloat16(r2);
}

// ---- coalesced tiled split of inputs [B, DIN, T] -> split rows (b*T+t, k) --
__global__ void split_a_mlp_t_kernel(const float* __restrict__ In) {
    __shared__ float tile[32][33];
    int b  = blockIdx.x;
    int t0 = blockIdx.y * 32;
    int k0 = blockIdx.z * 32;
#pragma unroll
    for (int i = 0; i < 4; i++) {
        int k = k0 + threadIdx.y + i * 8;
        int t = t0 + threadIdx.x;
        float v = 0.f;
        if (k < DIN && t < T_STEPS)
            v = In[b * (DIN * T_STEPS) + k * T_STEPS + t];
        tile[threadIdx.y + i * 8][threadIdx.x] = v;
    }
    __syncthreads();
#pragma unroll
    for (int i = 0; i < 4; i++) {
        int t = t0 + threadIdx.y + i * 8;
        int k = k0 + threadIdx.x;
        if (t < T_STEPS) {
            float v = tile[threadIdx.x][threadIdx.y + i * 8];
            __nv_bfloat16 h, m, l;
            bsplit(v, h, m, l);
            int soff = (b * T_STEPS + t) * KP1 + k;
            g_Ah[soff] = h; g_Am[soff] = m; g_Al[soff] = l;
        }
    }
}

__global__ void split_w_kernel(const float* __restrict__ W, int N, int K, int KP) {
    int idx = blockIdx.x * blockDim.x + threadIdx.x;
    if (idx >= N * KP) return;
    int n = idx / KP, k = idx - n * KP;
    float v = (k < K) ? W[n * K + k] : 0.f;
    __nv_bfloat16 h, m, l;
    bsplit(v, h, m, l);
    g_Wh[idx] = h; g_Wm[idx] = m; g_Wl[idx] = l;
}

__global__ void zero_pad2_kernel() {
    int idx = blockIdx.x * blockDim.x + threadIdx.x;
    if (idx >= MROWS * (KP2 - HID)) return;
    int r = idx / (KP2 - HID), j = idx - r * (KP2 - HID);
    int off = r * KP2 + HID + j;
    g_Ah[off] = __float2bfloat16(0.f);
    g_Am[off] = __float2bfloat16(0.f);
    g_Al[off] = __float2bfloat16(0.f);
}

// ======================= mma.sync bf16x6 GEMM (double-buffered) =============
__device__ __forceinline__ uint32_t sm2u32(const void* p) {
    uint32_t a;
    asm("{ .reg .u64 t; cvta.to.shared.u64 t, %1; cvt.u32.u64 %0, t; }"
        : "=r"(a) : "l"(p));
    return a;
}

__device__ __forceinline__ void cp16(uint32_t dst, const void* src) {
    asm volatile("cp.async.cg.shared.global [%0], [%1], 16;"
                 :: "r"(dst), "l"(src) : "memory");
}
__device__ __forceinline__ void cp16z(uint32_t dst, const void* src, int sz) {
    asm volatile("cp.async.cg.shared.global [%0], [%1], 16, %2;"
                 :: "r"(dst), "l"(src), "r"(sz) : "memory");
}

#define LDMX4(r0, r1, r2, r3, addr) \
    asm volatile("ldmatrix.sync.aligned.m8n8.x4.shared.b16 {%0,%1,%2,%3}, [%4];" \
                 : "=r"(r0), "=r"(r1), "=r"(r2), "=r"(r3) : "r"(addr))

#define MMA16816(c, a, b0, b1) \
    asm volatile("mma.sync.aligned.m16n8k16.row.col.f32.bf16.bf16.f32 " \
                 "{%0,%1,%2,%3}, {%4,%5,%6,%7}, {%8,%9}, {%0,%1,%2,%3};" \
                 : "+f"((c)[0]), "+f"((c)[1]), "+f"((c)[2]), "+f"((c)[3]) \
                 : "r"((a)[0]), "r"((a)[1]), "r"((a)[2]), "r"((a)[3]), \
                   "r"(b0), "r"(b1))

__global__ void __launch_bounds__(256) mma_gemm_kernel(
    const float* __restrict__ bias, int csel, int N, int KP) {
    extern __shared__ char smem[];
    float* Cdst = bufsel(csel);
    uint32_t sb = sm2u32(smem);
    int tid = threadIdx.x, w = tid >> 5, lane = tid & 31;
    int m0 = blockIdx.x * 128, n0 = blockIdx.y * 64;   // m-fast (R15 best)

    const __nv_bfloat16* Asrc[3] = {g_Ah, g_Am, g_Al};
    const __nv_bfloat16* Bsrc[3] = {g_Wh, g_Wm, g_Wl};

    float ps[8][4], pc[8][4];
#pragma unroll
    for (int i = 0; i < 8; i++)
#pragma unroll
        for (int j = 0; j < 4; j++) { ps[i][j] = 0.f; pc[i][j] = 0.f; }

    int aRow = w * 16 + (lane & 7) + ((lane >> 3) & 1) * 8;
    int aCol = ((lane >> 4) & 1) * 16;
    int bRow = (lane & 7) + ((lane >> 4) & 1) * 8;
    int bCol = ((lane >> 3) & 1) * 16;

    const int nch = KP / 64;

    // ---- issue loads for chunk `ch` into buffer base `bo`
    auto issue_loads = [&](int ch, uint32_t bo) {
        const int k0 = ch * 64;
#pragma unroll
        for (int l = 0; l < 12; l++) {
            int e = tid + l * 256;
            int s = e >> 10, rem = e & 1023, m = rem >> 3, j = rem & 7;
            cp16(sb + bo + s * ASPL + m * ROWB + j * 16,
                 Asrc[s] + (size_t)(m0 + m) * KP + k0 + j * 8);
        }
#pragma unroll
        for (int l = 0; l < 6; l++) {
            int e = tid + l * 256;
            int s = e >> 9, rem = e & 511, n = rem >> 3, j = rem & 7;
            int nn = n0 + n;
            int ok = (nn < N);
            int nc = ok ? nn : (N - 1);      // clamp src in-bounds
            cp16z(sb + bo + SMEM_B0 + s * BSPL + n * ROWB + j * 16,
                  Bsrc[s] + (size_t)nc * KP + k0 + j * 8, ok ? 16 : 0);
        }
        asm volatile("cp.async.commit_group;" ::: "memory");
    };

    issue_loads(0, 0);
    asm volatile("cp.async.wait_group 0;" ::: "memory");
    __syncthreads();

    uint32_t cur = 0;
    for (int ch = 0; ch < nch; ch++) {
        uint32_t nxt = cur ^ BUFSZ;
        if (ch + 1 < nch) issue_loads(ch + 1, nxt);

        float acc[8][4];
#pragma unroll
        for (int i = 0; i < 8; i++)
#pragma unroll
            for (int j = 0; j < 4; j++) acc[i][j] = 0.f;

#pragma unroll
        for (int ks = 0; ks < 4; ks++) {
            uint32_t af[3][4];
#pragma unroll
            for (int s = 0; s < 3; s++)
                LDMX4(af[s][0], af[s][1], af[s][2], af[s][3],
                      sb + cur + s * ASPL + aRow * ROWB + ks * 32 + aCol);
#pragma unroll
            for (int q = 0; q < 4; q++) {
                uint32_t bfr[3][4];
#pragma unroll
                for (int s = 0; s < 3; s++)
                    LDMX4(bfr[s][0], bfr[s][1], bfr[s][2], bfr[s][3],
                          sb + cur + SMEM_B0 + s * BSPL + (q * 16 + bRow) * ROWB +
                          ks * 32 + bCol);
                const int pa[6] = {0, 2, 1, 0, 1, 0};
                const int pb[6] = {2, 0, 1, 1, 0, 0};
#pragma unroll
                for (int p = 0; p < 6; p++) {
                    MMA16816(acc[2 * q],     af[pa[p]], bfr[pb[p]][0], bfr[pb[p]][1]);
                    MMA16816(acc[2 * q + 1], af[pa[p]], bfr[pb[p]][2], bfr[pb[p]][3]);
                }
            }
        }
#pragma unroll
        for (int i = 0; i < 8; i++)
#pragma unroll
            for (int j = 0; j < 4; j++) kmerge(acc[i][j], ps[i][j], pc[i][j]);

        if (ch + 1 < nch)
            asm volatile("cp.async.wait_group 0;" ::: "memory");
        __syncthreads();
        cur = nxt;
    }

    int r = lane >> 2, cp = (lane & 3) * 2;
#pragma unroll
    for (int nb = 0; nb < 8; nb++) {
        int n = n0 + nb * 8 + cp;
        int m = m0 + w * 16 + r;
        if (n < N) {
            Cdst[(size_t)m * N + n] =
                __fadd_rn(__fsub_rn(ps[nb][0], pc[nb][0]), bias[n]);
            Cdst[(size_t)(m + 8) * N + n] =
                __fadd_rn(__fsub_rn(ps[nb][2], pc[nb][2]), bias[n]);
        }
        if (n + 1 < N) {
            Cdst[(size_t)m * N + n + 1] =
                __fadd_rn(__fsub_rn(ps[nb][1], pc[nb][1]), bias[n + 1]);
            Cdst[(size_t)(m + 8) * N + n + 1] =
                __fadd_rn(__fsub_rn(ps[nb][3], pc[nb][3]), bias[n + 1]);
        }
    }
}

// ------------------------- BN stats: fp64, 16 rows per block ----------------
__global__ void bn_stats_kernel() {
    int blk = blockIdx.x;
    int tid = threadIdx.x;
    double ls[4] = {0.0, 0.0, 0.0, 0.0};
    double lq[4] = {0.0, 0.0, 0.0, 0.0};
    int r0 = blk * (MROWS / NSTATB);
    for (int rr = 0; rr < MROWS / NSTATB; rr += 4) {
        float v[4][4];
#pragma unroll
        for (int u = 0; u < 4; u++) {
            const float* row = g_buf0 + (size_t)(r0 + rr + u) * DIN;
#pragma unroll
            for (int j = 0; j < 4; j++) {
                int c = tid + j * 256;
                v[u][j] = (c < DIN) ? row[c] : 0.f;
            }
        }
#pragma unroll
        for (int u = 0; u < 4; u++)
#pragma unroll
            for (int j = 0; j < 4; j++) {
                double d = (double)v[u][j];
                ls[j] += d;
                lq[j] += d * d;
            }
    }
#pragma unroll
    for (int j = 0; j < 4; j++) {
        int c = tid + j * 256;
        if (c < DIN) {
            g_psumd[blk * DIN + c] = ls[j];
            g_psqd [blk * DIN + c] = lq[j];
        }
    }
}

__global__ void bn_fin_kernel() {
    int c = blockIdx.x * blockDim.x + threadIdx.x;
    if (c >= DIN) return;
    double s = 0.0, q = 0.0;
    for (int i = 0; i < NSTATB; i++) {
        s += g_psumd[i * DIN + c];
        q += g_psqd [i * DIN + c];
    }
    float sumf = (float)s;
    g_mean[c] = __fdiv_rn(sumf, (float)MROWS);
    double meand = s / (double)MROWS;
    double vard = q / (double)MROWS - meand * meand;
    float var = (float)vard;
    g_rs[c] = rsqrtf(__fadd_rn(var, EPS_BN));
}

// ------- fused BN apply + sigmoid + axon1, 2 channels/thread, bf16 out ------
__global__ void axon1_bn_split_kernel(const float* __restrict__ gamma,
                                      const float* __restrict__ beta,
                                      const float* __restrict__ a1,
                                      const float* __restrict__ a2) {
    const int HD = DIN / 2;
    int idx = blockIdx.x * blockDim.x + threadIdx.x;
    if (idx >= BATCH * HD) return;
    int b = idx / HD, c2 = idx - b * HD;
    int c = c2 * 2;
    float A1x = a1[c], A1y = a1[c + 1];
    float A2x = a2[c], A2y = a2[c + 1];
    float mnx = g_mean[c], mny = g_mean[c + 1];
    float rsx = g_rs[c], rsy = g_rs[c + 1];
    float gmx = gamma[c], gmy = gamma[c + 1];
    float btx = beta[c], bty = beta[c + 1];
    float p1x = 0.f, p2x = 0.f, p1y = 0.f, p2y = 0.f;
    const float2* src = reinterpret_cast<const float2*>(
        g_buf0 + (size_t)b * T_STEPS * DIN + c);
    __nv_bfloat162* dh = reinterpret_cast<__nv_bfloat162*>(
        g_Ah + (size_t)b * T_STEPS * KP1 + c);
    __nv_bfloat162* dm = reinterpret_cast<__nv_bfloat162*>(
        g_Am + (size_t)b * T_STEPS * KP1 + c);
    __nv_bfloat162* dl = reinterpret_cast<__nv_bfloat162*>(
        g_Al + (size_t)b * T_STEPS * KP1 + c);
    for (int t = 0; t < T_STEPS; t++) {
        float2 z = *src;
        src += DIN / 2;
        float vx = __fadd_rn(__fmul_rn(__fmul_rn(gmx, __fsub_rn(z.x, mnx)), rsx), btx);
        float vy = __fadd_rn(__fmul_rn(__fmul_rn(gmy, __fsub_rn(z.y, mny)), rsy), bty);
        float xx = sigmoid_exact(vx);
        float xy = sigmoid_exact(vy);
        float px = __fadd_rn(__fadd_rn(__fmul_rn(A1x, p1x), __fmul_rn(A2x, p2x)), xx);
        float py = __fadd_rn(__fadd_rn(__fmul_rn(A1y, p1y), __fmul_rn(A2y, p2y)), xy);
        __nv_bfloat16 hx, mx, lx, hy, my, ly;
        bsplit(px, hx, mx, lx);
        bsplit(py, hy, my, ly);
        __nv_bfloat162 hv; hv.x = hx; hv.y = hy;
        __nv_bfloat162 mv; mv.x = mx; mv.y = my;
        __nv_bfloat162 lv; lv.x = lx; lv.y = ly;
        *dh = hv; *dm = mv; *dl = lv;
        dh += KP1 / 2; dm += KP1 / 2; dl += KP1 / 2;
        p2x = p1x; p1x = px;
        p2y = p1y; p1y = py;
    }
}

// ---- fused LIF + mask + axon, 2 ch/thread, writes bf16x3 (KP2 layout) ------
__global__ void lif_axon_split_kernel(int bsel, const float* __restrict__ mask,
                                      const float* __restrict__ a1,
                                      const float* __restrict__ a2) {
    const int HD = HID / 2;
    float* buf = bufsel(bsel);
    int idx = blockIdx.x * blockDim.x + threadIdx.x;
    if (idx >= BATCH * HD) return;
    int b = idx / HD, c2 = idx - b * HD;
    int c = c2 * 2;
    float A1x = a1[c], A1y = a1[c + 1];
    float A2x = a2[c], A2y = a2[c + 1];
    float vx = 0.f, spx = 0.f, vy = 0.f, spy = 0.f;
    float p1x = 0.f, p2x = 0.f, p1y = 0.f, p2y = 0.f;
    const float2* src = reinterpret_cast<const float2*>(
        buf + (size_t)b * T_STEPS * HID + c);
    __nv_bfloat162* dh = reinterpret_cast<__nv_bfloat162*>(
        g_Ah + (size_t)b * T_STEPS * KP2 + c);
    __nv_bfloat162* dm = reinterpret_cast<__nv_bfloat162*>(
        g_Am + (size_t)b * T_STEPS * KP2 + c);
    __nv_bfloat162* dl = reinterpret_cast<__nv_bfloat162*>(
        g_Al + (size_t)b * T_STEPS * KP2 + c);
    const float* mrow0 = mask + (size_t)(b * HID + c) * T_STEPS;
    const float* mrow1 = mrow0 + T_STEPS;
    for (int t = 0; t < T_STEPS; t++) {
        float2 z = *src;
        src += HID / 2;
        vx = __fadd_rn(__fmul_rn(__fmul_rn(DECAY_M, vx), __fsub_rn(1.0f, spx)), z.x);
        vy = __fadd_rn(__fmul_rn(__fmul_rn(DECAY_M, vy), __fsub_rn(1.0f, spy)), z.y);
        spx = (vx > 1.0f) ? 1.0f : 0.0f;
        spy = (vy > 1.0f) ? 1.0f : 0.0f;
        float xx = __fmul_rn(spx, mrow0[t]);
        float xy = __fmul_rn(spy, mrow1[t]);
        float px = __fadd_rn(__fadd_rn(__fmul_rn(A1x, p1x), __fmul_rn(A2x, p2x)), xx);
        float py = __fadd_rn(__fadd_rn(__fmul_rn(A1y, p1y), __fmul_rn(A2y, p2y)), xy);
        __nv_bfloat16 hx, mx, lx, hy, my, ly;
        bsplit(px, hx, mx, lx);
        bsplit(py, hy, my, ly);
        __nv_bfloat162 hv; hv.x = hx; hv.y = hy;
        __nv_bfloat162 mv; mv.x = mx; mv.y = my;
        __nv_bfloat162 lv; lv.x = lx; lv.y = ly;
        *dh = hv; *dm = mv; *dl = lv;
        dh += KP2 / 2; dm += KP2 / 2; dl += KP2 / 2;
        p2x = p1x; p1x = px;
        p2y = p1y; p1y = py;
    }
}

// ---- fused LIF + mask + axon, 2 ch/thread, fp32 out (feeds gemm3) ----------
__global__ void lif_axon_kernel(int bsel, const float* __restrict__ mask,
                                const float* __restrict__ a1,
                                const float* __restrict__ a2) {
    const int HD = HID / 2;
    float* buf = bufsel(bsel);
    int idx = blockIdx.x * blockDim.x + threadIdx.x;
    if (idx >= BATCH * HD) return;
    int b = idx / HD, c2 = idx - b * HD;
    int c = c2 * 2;
    float A1x = a1[c], A1y = a1[c + 1];
    float A2x = a2[c], A2y = a2[c + 1];
    float vx = 0.f, spx = 0.f, vy = 0.f, spy = 0.f;
    float p1x = 0.f, p2x = 0.f, p1y = 0.f, p2y = 0.f;
    float2* src = reinterpret_cast<float2*>(buf + (size_t)b * T_STEPS * HID + c);
    const float* mrow0 = mask + (size_t)(b * HID + c) * T_STEPS;
    const float* mrow1 = mrow0 + T_STEPS;
    for (int t = 0; t < T_STEPS; t++) {
        float2 z = *src;
        vx = __fadd_rn(__fmul_rn(__fmul_rn(DECAY_M, vx), __fsub_rn(1.0f, spx)), z.x);
        vy = __fadd_rn(__fmul_rn(__fmul_rn(DECAY_M, vy), __fsub_rn(1.0f, spy)), z.y);
        spx = (vx > 1.0f) ? 1.0f : 0.0f;
        spy = (vy > 1.0f) ? 1.0f : 0.0f;
        float px = __fadd_rn(__fadd_rn(__fmul_rn(A1x, p1x), __fmul_rn(A2x, p2x)),
                             __fmul_rn(spx, mrow0[t]));
        float py = __fadd_rn(__fadd_rn(__fmul_rn(A1y, p1y), __fmul_rn(A2y, p2y)),
                             __fmul_rn(spy, mrow1[t]));
        float2 o; o.x = px; o.y = py;
        *src = o;
        src += HID / 2;
        p2x = p1x; p1x = px;
        p2y = p1y; p1y = py;
    }
}

// ------------------------- GEMM3 (N=10): compensated ------------------------
__global__ void __launch_bounds__(256) gemm3_kernel(
    const float* __restrict__ W3, const float* __restrict__ b3) {
    __shared__ float sW[NOUT][HID];
    int tid = threadIdx.x;
    for (int i = tid; i < NOUT * HID; i += 256) sW[i / HID][i % HID] = W3[i];
    __syncthreads();
    int idx = blockIdx.x * 256 + tid;
    int r = idx / NOUT, o = idx - r * NOUT;
    const float* a = g_buf2 + r * HID;
    float s = 0.f, c = 0.f;
    for (int k = 0; k < HID; k++) kacc2(a[k], sW[o][k], s, c);
    float acc = __fsub_rn(s, c);
    g_buf3[r * NOUT + o] = __fadd_rn(acc, b3[o]);
}

// ------------------------- final LIF + output transpose [B,10,T] ------------
__global__ void lif3_out_kernel(float* __restrict__ out) {
    int idx = blockIdx.x * blockDim.x + threadIdx.x;
    if (idx >= BATCH * NOUT) return;
    int b = idx / NOUT, o = idx - b * NOUT;
    float v = 0.f, s = 0.f;
    for (int t = 0; t < T_STEPS; t++) {
        float z = g_buf3[(b * T_STEPS + t) * NOUT + o];
        v = __fadd_rn(__fmul_rn(__fmul_rn(DECAY_M, v), __fsub_rn(1.0f, s)), z);
        s = (v > 1.0f) ? 1.0f : 0.0f;
        out[(b * NOUT + o) * T_STEPS + t] = s;
    }
}

// ------------------------- launch -------------------------------------------
extern "C" void kernel_launch(void* const* d_in, const int* in_sizes, int n_in,
                              void* d_out, int out_size) {
    const float* inputs = (const float*)d_in[0];
    const float* W_mlp  = (const float*)d_in[1];
    const float* b_mlp  = (const float*)d_in[2];
    const float* gamma  = (const float*)d_in[3];
    const float* beta   = (const float*)d_in[4];
    const float* a1_1   = (const float*)d_in[5];
    const float* a2_1   = (const float*)d_in[6];
    const float* W1     = (const float*)d_in[7];
    const float* b1     = (const float*)d_in[8];
    const float* a1_2   = (const float*)d_in[9];
    const float* a2_2   = (const float*)d_in[10];
    const float* W2     = (const float*)d_in[11];
    const float* b2     = (const float*)d_in[12];
    const float* a1_3   = (const float*)d_in[13];
    const float* a2_3   = (const float*)d_in[14];
    const float* W3     = (const float*)d_in[15];
    const float* b3     = (const float*)d_in[16];
    const float* mask1  = (const float*)d_in[17];
    const float* mask2  = (const float*)d_in[18];
    float* out = (float*)d_out;

    static int smem_set = 0;
    if (!smem_set) {
        cudaFuncSetAttribute(mma_gemm_kernel,
                             cudaFuncAttributeMaxDynamicSharedMemorySize, SMEM_TOT);
        smem_set = 1;
    }

    // ---- GEMM MLP  (grid: x = m-tiles, measured best)
    split_a_mlp_t_kernel<<<dim3(BATCH, 7, 26), dim3(32, 8)>>>(inputs);
    split_w_kernel<<<(DIN * KP1 + 255) / 256, 256>>>(W_mlp, DIN, DIN, KP1);
    mma_gemm_kernel<<<dim3(MROWS / 128, (DIN + 63) / 64), 256, SMEM_TOT>>>(
        b_mlp, 0, DIN, KP1);

    bn_stats_kernel<<<NSTATB, 256>>>();
    bn_fin_kernel<<<(DIN + 255) / 256, 256>>>();
    axon1_bn_split_kernel<<<(BATCH * (DIN / 2) + 255) / 256, 256>>>(
        gamma, beta, a1_1, a2_1);

    // ---- GEMM1
    split_w_kernel<<<(HID * KP1 + 255) / 256, 256>>>(W1, HID, DIN, KP1);
    mma_gemm_kernel<<<dim3(MROWS / 128, (HID + 63) / 64), 256, SMEM_TOT>>>(
        b1, 1, HID, KP1);
    lif_axon_split_kernel<<<(BATCH * (HID / 2) + 255) / 256, 256>>>(
        1, mask1, a1_2, a2_2);
    zero_pad2_kernel<<<(MROWS * (KP2 - HID) + 255) / 256, 256>>>();

    // ---- GEMM2
    split_w_kernel<<<(HID * KP2 + 255) / 256, 256>>>(W2, HID, HID, KP2);
    mma_gemm_kernel<<<dim3(MROWS / 128, (HID + 63) / 64), 256, SMEM_TOT>>>(
        b2, 2, HID, KP2);
    lif_axon_kernel<<<(BATCH * (HID / 2) + 255) / 256, 256>>>(
        2, mask2, a1_3, a2_3);

    // ---- GEMM3 + output
    gemm3_kernel<<<MROWS * NOUT / 256, 256>>>(W3, b3);
    lif3_out_kernel<<<(BATCH * NOUT + 255) / 256, 256>>>(out);
}